// round 13
// baseline (speedup 1.0000x reference)
#include <cuda_runtime.h>
#include <cstdint>

// Problem constants: B=8, S=4096, H=16, E=64, s=64
#define NB 8
#define NH 16
#define NE 64
#define STOT 4096

#define TWO_PI 6.283185307179586476925f

__device__ float g_Mt[NH * 64 * 64];   // TRANSPOSED operator: g_Mt[h][j][n]
__device__ int   g_ready[NH];          // monotone per-head chunk counter (8)

__device__ __forceinline__ uint32_t s2u(const void* p) {
    return (uint32_t)__cvta_generic_to_shared(p);
}
__device__ __forceinline__ void cp16(float* dst, const float* src) {
    asm volatile("cp.async.cg.shared.global [%0], [%1], 16;"
                 :: "r"(s2u(dst)), "l"(src));
}
__device__ __forceinline__ void cp4(float* dst, const float* src) {
    asm volatile("cp.async.ca.shared.global [%0], [%1], 4;"
                 :: "r"(s2u(dst)), "l"(src));
}
__device__ __forceinline__ unsigned long long pack2(float x, float y) {
    unsigned long long r;
    asm("mov.b64 %0, {%1, %2};" : "=l"(r) : "f"(x), "f"(y));
    return r;
}
__device__ __forceinline__ void unpack2(float& x, float& y, unsigned long long v) {
    asm("mov.b64 {%0, %1}, %2;" : "=f"(x), "=f"(y) : "l"(v));
}
__device__ __forceinline__ unsigned long long ffma2(unsigned long long m,
                                                    unsigned long long a,
                                                    unsigned long long c) {
    unsigned long long d;
    asm("fma.rn.f32x2 %0, %1, %2, %3;" : "=l"(d) : "l"(m), "l"(a), "l"(c));
    return d;
}

// ---------------------------------------------------------------------------
// Single fused kernel: 256 blocks = (b,h,e-half), 512 threads, ~84KB dyn smem
// -> 2 CTAs/SM, all 256 CTAs co-resident (deadlock-free handshake).
//
// STAGGERED prologue (fills the chip-wide read->write DRAM valley):
//   eh==0 (128 blocks): stage 2 il-rows via cp.async, build 8 rows of M_h
//     (chunk c=b; factored form, incremental roots), publish via red.release,
//     consume staged rows, stream il=2..15.
//   eh==1 (128 blocks): NO prologue - start streaming il=0..15 at t=0.
//     They run ~3us ahead, so their write phase overlaps eh==0's read phase.
//
// Phase 1: direct-LDG register-tile reduce (no atomics, no in-loop syncs).
// Phase 2: matvec with fma.rn.f32x2 pairs (Msh fetched during combine).
// z_pb   : emitted BEFORE phase 3 (overlaps the chip write phase).
// Phase 3: streaming float4 stores.
// ---------------------------------------------------------------------------
__global__ __launch_bounds__(512, 2)
void fftbias_fused(const float* __restrict__ v,
                   const float* __restrict__ w,
                   const float* __restrict__ o_,
                   float* __restrict__ out,
                   float* __restrict__ out2) {
    const int bx = blockIdx.x;
    const int b  = bx >> 5;
    const int h  = (bx >> 1) & 15;
    const int eh = bx & 1;                 // e-half
    const int tid  = threadIdx.x;
    const int lane = tid & 31;             // local e (0..31)
    const int wp   = tid >> 5;             // warp 0..15
    const int jg   = wp & 3;               // j-group (16 j's)
    const int ig   = wp >> 2;              // i-group (16 i's)

    extern __shared__ float sm[];
    float* vpart = sm;                     // [4][32][68] = 8704
    float* upart = sm + 8704;              // [4][32][68] = 8704
    float* Msh   = sm + 17408;             // [64 j][64 n] = 4096 (transposed)
    // staging aliases (dead during builder):
    float* stg0  = upart;                  // il=0: 16 jl x 512
    float* stg1a = Msh;                    // il=1, jl 0..7:  8 x 512
    float* stg1b = vpart + 4608;           // il=1, jl 8..15: 8 x 512
    // aliases (live after the reduction):
    float* vs  = vpart;                    // [32][68]
    float* us  = upart;                    // [32][68]
    float* rvs = vpart + 2304;             // [64][32]
    float* rus = vpart + 4352;             // [64][32]
    __shared__ float osh[64];
    __shared__ float zp[64];

    const float* vb = v + ((size_t)b * STOT * NH + h) * NE + eh * 32;
    const float* base = vb + lane;

    if (tid < 64) osh[tid] = o_[tid];

    float vacc[16], uacc[16];

    if (eh == 0) {
        // ---- stage il=0 and il=1 rows into builder-dead smem ---------------
        {
            const float* r0 = base + (size_t)(ig * 16 * 64 + jg * 16) * 1024;
            const float* r1 = r0 + (size_t)64 * 1024;
            #pragma unroll
            for (int jl = 0; jl < 16; ++jl)
                cp4(stg0 + jl * 512 + tid, r0 + (size_t)jl * 1024);
            #pragma unroll
            for (int jl = 0; jl < 8; ++jl)
                cp4(stg1a + jl * 512 + tid, r1 + (size_t)jl * 1024);
            #pragma unroll
            for (int jl = 8; jl < 16; ++jl)
                cp4(stg1b + (jl - 8) * 512 + tid, r1 + (size_t)jl * 1024);
            asm volatile("cp.async.commit_group;");
        }

        // ---- Builder: chunk c = b (8 n-rows of M_h) ------------------------
        {
            const int c = b;               // chunk 0..7, rows n = c*8 .. c*8+7
            // scratch in vpart[0..2944) (staging uses vpart[4608..])
            float2* root127 = (float2*)vpart;              // 128 f2  @0
            float2* root126 = root127 + 128;               // 128 f2  @256
            float2* Zpart   = root126 + 128;               // 512 f2  @512
            float2* Zsh     = Zpart + 512;                 // 64 f2   @1536
            float2* Ash     = Zsh + 64;                    // 64 f2   @1664
            float*  zsh     = (float*)(Ash + 64);          // 128 f   @1792
            float2* Psh     = (float2*)(zsh + 128);        // 512 f2  @1920..2944

            if (tid < 127) {
                float sv, cv;
                __sincosf(TWO_PI * (float)tid / 127.0f, &sv, &cv);
                root127[tid] = make_float2(cv, sv);
                zsh[tid] = w[h * 127 + tid];
            }
            if (tid < 126) {
                float sv, cv;
                __sincosf(TWO_PI * (float)tid / 126.0f, &sv, &cv);
                root126[tid] = make_float2(cv, sv);
            }
            __syncthreads();

            // Z[k]: 8 u-chunks of 16 in parallel
            {
                const int k  = tid & 63;
                const int uc = tid >> 6;   // 0..7
                const int u0 = uc * 16;
                int m = (k * u0) % 127;
                float zr = 0.f, zi = 0.f;
                #pragma unroll
                for (int s = 0; s < 16; ++s) {
                    int u = u0 + s;
                    if (u < 127) {
                        float2 rt = root127[m];
                        float zu = zsh[u];
                        zr += zu * rt.x;
                        zi -= zu * rt.y;
                    }
                    m += k; if (m >= 127) m -= 127;
                }
                Zpart[uc * 64 + k] = make_float2(zr, zi);
            }
            __syncthreads();
            if (tid < 64) {
                float zr = 0.f, zi = 0.f;
                #pragma unroll
                for (int uc = 0; uc < 8; ++uc) {
                    float2 p = Zpart[uc * 64 + tid];
                    zr += p.x; zi += p.y;
                }
                Zsh[tid] = make_float2(zr, zi);
                // A[k] = c_k/126 * Z[k] * conj(w127^{63k})
                float2 r = root127[(63 * tid) % 127];
                float ck = (tid == 0 || tid == 63) ? (1.0f / 126.0f)
                                                   : (2.0f / 126.0f);
                Ash[tid] = make_float2(ck * (zr * r.x + zi * r.y),
                                       ck * (zi * r.x - zr * r.y));
            }
            __syncthreads();
            // P[nl][k] = A[k] * w126^{kn}, 8 nl x 64 k = 512 (one per thread)
            {
                const int k = tid & 63, nl = tid >> 6;
                const int n = c * 8 + nl;
                float2 a = Ash[k];
                float2 f = root126[(k * n) % 126];
                Psh[nl * 64 + k] = make_float2(a.x * f.x - a.y * f.y,
                                               a.x * f.y + a.y * f.x);
            }
            __syncthreads();

            // M[n][j] = Re sum_k P[nl][k] conj(w127^{kj}); incremental roots
            {
                const int nl = tid >> 6;
                const int j  = tid & 63;
                const int n  = c * 8 + nl;
                float2 r  = make_float2(1.0f, 0.0f);
                float2 mj = root127[j];
                float acc = 0.f;
                const float2* Pp = Psh + nl * 64;
                #pragma unroll 8
                for (int k = 0; k < 64; ++k) {
                    float2 Pv = Pp[k];             // warp-broadcast LDS.64
                    acc = fmaf(Pv.x, r.x, acc);
                    acc = fmaf(Pv.y, r.y, acc);    // Re(P * conj(r))
                    float nx = r.x * mj.x - r.y * mj.y;
                    r.y = fmaf(r.x, mj.y, r.y * mj.x);
                    r.x = nx;
                }
                g_Mt[h * 4096 + j * 64 + n] = acc;
            }
            __syncthreads();               // scratch dead; STGs issued
            if (tid == 0) {
                asm volatile("red.release.gpu.global.add.s32 [%0], %1;"
                             :: "l"(&g_ready[h]), "r"(1) : "memory");
            }
        }

        // ---- consume staged il=0,1 rows ------------------------------------
        asm volatile("cp.async.wait_group 0;");
        {
            float us0 = 0.f, us1 = 0.f;
            #pragma unroll
            for (int jl = 0; jl < 16; ++jl) {
                float x0 = stg0[jl * 512 + tid];
                float x1 = (jl < 8) ? stg1a[jl * 512 + tid]
                                    : stg1b[(jl - 8) * 512 + tid];
                vacc[jl] = x0 + x1;
                us0 += x0;
                us1 += x1;
            }
            uacc[0] = us0;
            uacc[1] = us1;
            #pragma unroll
            for (int k = 2; k < 16; ++k) uacc[k] = 0.f;
        }
        __syncthreads();                   // staging regions now reusable

        // ---- Phase 1 (il = 2..15) ------------------------------------------
        #pragma unroll
        for (int il = 2; il < 16; ++il) {
            const float* rowp =
                base + (size_t)((ig * 16 + il) * 64 + jg * 16) * 1024;
            #pragma unroll
            for (int jl = 0; jl < 16; ++jl) {
                float x = __ldcs(rowp + (size_t)jl * 1024);
                vacc[jl] += x;
                uacc[il] += x;
            }
        }
    } else {
        // ---- eh==1: no prologue - stream immediately (il = 0..15) ----------
        #pragma unroll
        for (int k = 0; k < 16; ++k) { vacc[k] = 0.f; uacc[k] = 0.f; }
        #pragma unroll
        for (int il = 0; il < 16; ++il) {
            const float* rowp =
                base + (size_t)((ig * 16 + il) * 64 + jg * 16) * 1024;
            #pragma unroll
            for (int jl = 0; jl < 16; ++jl) {
                float x = __ldcs(rowp + (size_t)jl * 1024);
                vacc[jl] += x;
                uacc[il] += x;
            }
        }
    }

    #pragma unroll
    for (int q4 = 0; q4 < 4; ++q4) {       // STS.128, conflict-free
        *(float4*)&vpart[(ig * 32 + lane) * 68 + jg * 16 + q4 * 4] =
            make_float4(vacc[q4*4], vacc[q4*4+1], vacc[q4*4+2], vacc[q4*4+3]);
        *(float4*)&upart[(jg * 32 + lane) * 68 + ig * 16 + q4 * 4] =
            make_float4(uacc[q4*4], uacc[q4*4+1], uacc[q4*4+2], uacc[q4*4+3]);
    }
    __syncthreads();

    // ---- spin for M (published long ago), then fetch during combine --------
    if (tid == 0) {
        int rdy;
        do {
            asm volatile("ld.acquire.gpu.global.b32 %0, [%1];"
                         : "=r"(rdy) : "l"(&g_ready[h]) : "memory");
        } while (rdy < 8);
    }
    __syncthreads();

    {
        const float* Msrc = g_Mt + h * 4096;
        cp16(Msh + tid * 8,     Msrc + tid * 8);
        cp16(Msh + tid * 8 + 4, Msrc + tid * 8 + 4);
        asm volatile("cp.async.commit_group;");
    }

    // 4-way combine (partials at stride 2176 = 32*68)
    #pragma unroll
    for (int k = 0; k < 4; ++k) {
        int s  = tid + k * 512;            // 0..2047
        int ee = s >> 6, xx = s & 63;
        int o = ee * 68 + xx;
        float a = vpart[o] + vpart[2176 + o] + vpart[4352 + o] + vpart[6528 + o];
        float c = upart[o] + upart[2176 + o] + upart[4352 + o] + upart[6528 + o];
        vs[o] = a;                         // own slot (== vpart[0] copy)
        us[o] = c;
    }
    asm volatile("cp.async.wait_group 0;");
    __syncthreads();

    // ---- Phase 2: f32x2-paired matvec; thread owns e=lane, n = wp*4..+3 ----
    unsigned long long accv[2] = {0ull, 0ull};
    unsigned long long accu[2] = {0ull, 0ull};

    #pragma unroll 4
    for (int j4 = 0; j4 < 16; ++j4) {
        float4 va = *(const float4*)&vs[lane * 68 + j4 * 4];
        float4 ua = *(const float4*)&us[lane * 68 + j4 * 4];
        #pragma unroll
        for (int jj = 0; jj < 4; ++jj) {
            float a  = (&va.x)[jj];
            float bb = (&ua.x)[jj];
            unsigned long long aa = pack2(a, a);
            unsigned long long bp = pack2(bb, bb);
            const float* mrow = &Msh[(j4 * 4 + jj) * 64 + wp * 4];
            #pragma unroll
            for (int p = 0; p < 2; ++p) {
                unsigned long long mm =
                    *(const unsigned long long*)(mrow + p * 2);  // bcast LDS.64
                accv[p] = ffma2(mm, aa, accv[p]);
                accu[p] = ffma2(mm, bp, accu[p]);
            }
        }
    }
    #pragma unroll
    for (int p = 0; p < 2; ++p) {
        float r0, r1, s0, s1;
        unpack2(r0, r1, accv[p]);
        unpack2(s0, s1, accu[p]);
        const int n0 = wp * 4 + p * 2;
        rvs[n0 * 32 + lane]       = r0;
        rvs[(n0 + 1) * 32 + lane] = r1;
        rus[n0 * 32 + lane]       = s0;
        rus[(n0 + 1) * 32 + lane] = s1;
    }
    __syncthreads();

    // ---- z_pb (b==0, eh==0): BEFORE phase 3 so it overlaps chip writes -----
    if (b == 0 && eh == 0) {
        if (tid < 64) {
            float acc = 0.f;
            #pragma unroll
            for (int j = 0; j < 64; ++j) acc += Msh[j * 64 + tid] * osh[j];
            zp[tid] = 64.0f * acc;
        }
        __syncthreads();
        for (int idx = tid; idx < 4096; idx += 512) {
            int i = idx >> 6, j = idx & 63;
            out2[(size_t)idx * 16 + h] = zp[j] + zp[i];
        }
    }

    // ---- Phase 3: streaming float4 output ----------------------------------
    const int q  = tid & 7;                // float4 slot within 32-e half
    const int rg = tid >> 3;               // 0..63 (j)
    float* ob = out + ((size_t)b * STOT * NH + h) * NE + eh * 32;
    float4 a4 = *(const float4*)&rvs[rg * 32 + q * 4];   // j = rg, invariant
    #pragma unroll 4
    for (int r = 0; r < 64; ++r) {         // i = r
        float4 c4 = *(const float4*)&rus[r * 32 + q * 4];
        float4 o4 = make_float4(a4.x + c4.x, a4.y + c4.y, a4.z + c4.z, a4.w + c4.w);
        __stcs((float4*)&ob[((size_t)(r * 64 + rg)) * 1024 + q * 4], o4);
    }
}

// ---------------------------------------------------------------------------
extern "C" void kernel_launch(void* const* d_in, const int* in_sizes, int n_in,
                              void* d_out, int out_size) {
    const float* v  = (const float*)d_in[0];   // (8,4096,16,64) f32
    const float* w  = (const float*)d_in[1];   // (1,16,127) f32
    const float* o_ = (const float*)d_in[2];   // (64,) f32
    float* out  = (float*)d_out;
    float* out2 = out + (size_t)NB * STOT * NH * NE;   // z_pb region

    const int smem_bytes = (8704 * 2 + 4096) * 4;      // 86016 B -> 2 CTAs/SM

    cudaFuncSetAttribute(fftbias_fused,
                         cudaFuncAttributeMaxDynamicSharedMemorySize, smem_bytes);

    fftbias_fused<<<NB * NH * 2, 512, smem_bytes>>>(v, w, o_, out, out2);
}

// round 15
// speedup vs baseline: 1.0376x; 1.0376x over previous
#include <cuda_runtime.h>
#include <cstdint>

// Problem constants: B=8, S=4096, H=16, E=64, s=64
#define NB 8
#define NH 16
#define NE 64
#define STOT 4096

#define TWO_PI 6.283185307179586476925f

__device__ float g_Mt[NH * 64 * 64];   // TRANSPOSED operator: g_Mt[h][j][n]
__device__ int   g_ready[NH];          // monotone per-head chunk counter (16)

__device__ __forceinline__ uint32_t s2u(const void* p) {
    return (uint32_t)__cvta_generic_to_shared(p);
}
__device__ __forceinline__ void cp16(float* dst, const float* src) {
    asm volatile("cp.async.cg.shared.global [%0], [%1], 16;"
                 :: "r"(s2u(dst)), "l"(src));
}
__device__ __forceinline__ void cp4(float* dst, const float* src) {
    asm volatile("cp.async.ca.shared.global [%0], [%1], 4;"
                 :: "r"(s2u(dst)), "l"(src));
}
__device__ __forceinline__ unsigned long long pack2(float x, float y) {
    unsigned long long r;
    asm("mov.b64 %0, {%1, %2};" : "=l"(r) : "f"(x), "f"(y));
    return r;
}
__device__ __forceinline__ void unpack2(float& x, float& y, unsigned long long v) {
    asm("mov.b64 {%0, %1}, %2;" : "=f"(x), "=f"(y) : "l"(v));
}
__device__ __forceinline__ unsigned long long ffma2(unsigned long long m,
                                                    unsigned long long a,
                                                    unsigned long long c) {
    unsigned long long d;
    asm("fma.rn.f32x2 %0, %1, %2, %3;" : "=l"(d) : "l"(m), "l"(a), "l"(c));
    return d;
}

// ---------------------------------------------------------------------------
// Single fused kernel: 256 blocks = (b,h,e-half), 512 threads, ~84KB dyn smem
// -> 2 CTAs/SM, all 256 CTAs co-resident (deadlock-free handshake).
//
// Prologue: stage TWO il-rows (32x4B cp.async per thread) into builder-dead
//           smem so ~2.7us of DRAM streams DURING the builder.
// Builder (ALL blocks, chunk = b*2+eh, 4 n-rows): factored form
//   A[k] = c_k/126 Z[k] conj(w127^{63k}); P[nl][k] = A[k] w126^{kn};
//   M[n][j] = Re sum_k P[nl][k] conj(w127^{kj})  (incremental roots)
// stored TRANSPOSED to g_Mt[h][j][n]; publish via red.release.
//
// Phase 1: direct-LDG register-tile reduce (no atomics, no in-loop syncs).
// Then: ALL threads spin-acquire g_ready (one iteration; published ~20us ago)
// and issue the M cp.async BEFORE the partial stores, so the 16KB fetch
// overlaps stores + sync + combine instead of stalling wait_group.
// Phase 2: matvec with fma.rn.f32x2 pairs.
// z_pb (b==0,eh==0): before phase 3 so its stores overlap the chip writes.
// Phase 3: streaming float4 stores.
// ---------------------------------------------------------------------------
__global__ __launch_bounds__(512, 2)
void fftbias_fused(const float* __restrict__ v,
                   const float* __restrict__ w,
                   const float* __restrict__ o_,
                   float* __restrict__ out,
                   float* __restrict__ out2) {
    const int bx = blockIdx.x;
    const int b  = bx >> 5;
    const int h  = (bx >> 1) & 15;
    const int eh = bx & 1;                 // e-half
    const int tid  = threadIdx.x;
    const int lane = tid & 31;             // local e (0..31)
    const int wp   = tid >> 5;             // warp 0..15
    const int jg   = wp & 3;               // j-group (16 j's)
    const int ig   = wp >> 2;              // i-group (16 i's)

    extern __shared__ float sm[];
    float* vpart = sm;                     // [4][32][68] = 8704
    float* upart = sm + 8704;              // [4][32][68] = 8704
    float* Msh   = sm + 17408;             // [64 j][64 n] = 4096 (transposed)
    // staging aliases (dead during builder):
    float* stg0  = upart;                  // il=0: 16 jl x 512
    float* stg1a = Msh;                    // il=1, jl 0..7:  8 x 512
    float* stg1b = vpart + 4608;           // il=1, jl 8..15: 8 x 512
    // aliases (live after the reduction):
    float* vs  = vpart;                    // [32][68]
    float* us  = upart;                    // [32][68]
    float* rvs = vpart + 2304;             // [64][32]
    float* rus = vpart + 4352;             // [64][32]
    __shared__ float osh[64];
    __shared__ float zp[64];

    const float* vb = v + ((size_t)b * STOT * NH + h) * NE + eh * 32;
    const float* base = vb + lane;

    // ---- stage il=0 and il=1 rows into builder-dead smem -------------------
    {
        const float* r0 = base + (size_t)(ig * 16 * 64 + jg * 16) * 1024;
        const float* r1 = r0 + (size_t)64 * 1024;
        #pragma unroll
        for (int jl = 0; jl < 16; ++jl)
            cp4(stg0 + jl * 512 + tid, r0 + (size_t)jl * 1024);
        #pragma unroll
        for (int jl = 0; jl < 8; ++jl)
            cp4(stg1a + jl * 512 + tid, r1 + (size_t)jl * 1024);
        #pragma unroll
        for (int jl = 8; jl < 16; ++jl)
            cp4(stg1b + (jl - 8) * 512 + tid, r1 + (size_t)jl * 1024);
        asm volatile("cp.async.commit_group;");
    }

    if (tid < 64) osh[tid] = o_[tid];

    // ---- Builder (ALL blocks): chunk c = b*2+eh (4 n-rows of M_h) ----------
    {
        const int c = b * 2 + eh;
        // scratch in vpart[0..2944) (staging uses vpart[4608..])
        float2* root127 = (float2*)vpart;              // 128 f2  @0
        float2* root126 = root127 + 128;               // 128 f2  @256
        float2* Zpart   = root126 + 128;               // 512 f2  @512
        float2* Zsh     = Zpart + 512;                 // 64 f2   @1536
        float2* Ash     = Zsh + 64;                    // 64 f2   @1664
        float*  zsh     = (float*)(Ash + 64);          // 128 f   @1792
        float2* Psh     = (float2*)(zsh + 128);        // 256 f2  @1920
        float*  part    = (float*)(Psh + 256);         // 512 f   @2432..2944

        if (tid < 127) {
            float sv, cv;
            __sincosf(TWO_PI * (float)tid / 127.0f, &sv, &cv);
            root127[tid] = make_float2(cv, sv);
            zsh[tid] = w[h * 127 + tid];
        }
        if (tid < 126) {
            float sv, cv;
            __sincosf(TWO_PI * (float)tid / 126.0f, &sv, &cv);
            root126[tid] = make_float2(cv, sv);
        }
        __syncthreads();

        // Z[k]: 8 u-chunks of 16 in parallel
        {
            const int k  = tid & 63;
            const int uc = tid >> 6;       // 0..7
            const int u0 = uc * 16;
            int m = (k * u0) % 127;
            float zr = 0.f, zi = 0.f;
            #pragma unroll
            for (int s = 0; s < 16; ++s) {
                int u = u0 + s;
                if (u < 127) {
                    float2 rt = root127[m];
                    float zu = zsh[u];
                    zr += zu * rt.x;
                    zi -= zu * rt.y;
                }
                m += k; if (m >= 127) m -= 127;
            }
            Zpart[uc * 64 + k] = make_float2(zr, zi);
        }
        __syncthreads();
        if (tid < 64) {
            float zr = 0.f, zi = 0.f;
            #pragma unroll
            for (int uc = 0; uc < 8; ++uc) {
                float2 p = Zpart[uc * 64 + tid];
                zr += p.x; zi += p.y;
            }
            Zsh[tid] = make_float2(zr, zi);
            // A[k] = c_k/126 * Z[k] * conj(w127^{63k})
            float2 r = root127[(63 * tid) % 127];
            float ck = (tid == 0 || tid == 63) ? (1.0f / 126.0f) : (2.0f / 126.0f);
            Ash[tid] = make_float2(ck * (zr * r.x + zi * r.y),
                                   ck * (zi * r.x - zr * r.y));
        }
        __syncthreads();
        // P[nl][k] = A[k] * w126^{kn}
        if (tid < 256) {
            const int k = tid & 63, nl = tid >> 6;
            const int n = c * 4 + nl;
            float2 a = Ash[k];
            float2 f = root126[(k * n) % 126];
            Psh[nl * 64 + k] = make_float2(a.x * f.x - a.y * f.y,
                                           a.x * f.y + a.y * f.x);
        }
        __syncthreads();

        // M[n][j] = Re sum_k P[nl][k] conj(w127^{kj}); k-halved, incremental r
        {
            const int ent = tid & 255;
            const int kh  = tid >> 8;      // 0/1
            const int nl  = ent >> 6;
            const int j   = ent & 63;
            float2 r  = root127[(kh * 32 * j) % 127];
            float2 mj = root127[j];
            float acc = 0.f;
            const float2* Pp = Psh + nl * 64 + kh * 32;
            #pragma unroll
            for (int kk = 0; kk < 32; ++kk) {
                float2 Pv = Pp[kk];                // warp-broadcast LDS.64
                acc = fmaf(Pv.x, r.x, acc);
                acc = fmaf(Pv.y, r.y, acc);        // Re(P * conj(r))
                float nx = r.x * mj.x - r.y * mj.y;
                r.y = fmaf(r.x, mj.y, r.y * mj.x);
                r.x = nx;
            }
            part[tid] = acc;
        }
        __syncthreads();
        if (tid < 256) {
            const int nl = tid >> 6, j = tid & 63;
            const int n  = c * 4 + nl;
            g_Mt[h * 4096 + j * 64 + n] = part[tid] + part[tid + 256];
        }
        __syncthreads();                   // scratch dead; STGs issued
        if (tid == 0) {
            asm volatile("red.release.gpu.global.add.s32 [%0], %1;"
                         :: "l"(&g_ready[h]), "r"(1) : "memory");
        }
    }

    // ---- Phase 1: register-tile streaming reduce ---------------------------
    float vacc[16], uacc[16];

    // consume staged il=0,1 rows (own slots only)
    asm volatile("cp.async.wait_group 0;");
    {
        float us0 = 0.f, us1 = 0.f;
        #pragma unroll
        for (int jl = 0; jl < 16; ++jl) {
            float x0 = stg0[jl * 512 + tid];
            float x1 = (jl < 8) ? stg1a[jl * 512 + tid]
                                : stg1b[(jl - 8) * 512 + tid];
            vacc[jl] = x0 + x1;
            us0 += x0;
            us1 += x1;
        }
        uacc[0] = us0;
        uacc[1] = us1;
        #pragma unroll
        for (int k = 2; k < 16; ++k) uacc[k] = 0.f;
    }
    __syncthreads();                       // staging regions now reusable

    #pragma unroll
    for (int il = 2; il < 16; ++il) {
        const float* rowp =
            base + (size_t)((ig * 16 + il) * 64 + jg * 16) * 1024;
        #pragma unroll
        for (int jl = 0; jl < 16; ++jl) {
            float x = __ldcs(rowp + (size_t)jl * 1024);
            vacc[jl] += x;                 // v_s[e][jg*16+jl] partial (this ig)
            uacc[il] += x;                 // u_s[e][ig*16+il] partial (this jg)
        }
    }

    // ---- spin (all threads; M published ~20us ago) + EARLY M fetch ---------
    {
        int rdy;
        do {
            asm volatile("ld.acquire.gpu.global.b32 %0, [%1];"
                         : "=r"(rdy) : "l"(&g_ready[h]) : "memory");
        } while (rdy < 16);
        const float* Msrc = g_Mt + h * 4096;
        cp16(Msh + tid * 8,     Msrc + tid * 8);
        cp16(Msh + tid * 8 + 4, Msrc + tid * 8 + 4);
        asm volatile("cp.async.commit_group;");
    }

    #pragma unroll
    for (int q4 = 0; q4 < 4; ++q4) {       // STS.128, conflict-free
        *(float4*)&vpart[(ig * 32 + lane) * 68 + jg * 16 + q4 * 4] =
            make_float4(vacc[q4*4], vacc[q4*4+1], vacc[q4*4+2], vacc[q4*4+3]);
        *(float4*)&upart[(jg * 32 + lane) * 68 + ig * 16 + q4 * 4] =
            make_float4(uacc[q4*4], uacc[q4*4+1], uacc[q4*4+2], uacc[q4*4+3]);
    }
    __syncthreads();

    // 4-way combine (partials at stride 2176 = 32*68)
    #pragma unroll
    for (int k = 0; k < 4; ++k) {
        int s  = tid + k * 512;            // 0..2047
        int ee = s >> 6, xx = s & 63;
        int o = ee * 68 + xx;
        float a = vpart[o] + vpart[2176 + o] + vpart[4352 + o] + vpart[6528 + o];
        float c = upart[o] + upart[2176 + o] + upart[4352 + o] + upart[6528 + o];
        vs[o] = a;                         // own slot (== vpart[0] copy)
        us[o] = c;
    }
    asm volatile("cp.async.wait_group 0;");
    __syncthreads();

    // ---- Phase 2: f32x2-paired matvec; thread owns e=lane, n = wp*4..+3 ----
    unsigned long long accv[2] = {0ull, 0ull};
    unsigned long long accu[2] = {0ull, 0ull};

    #pragma unroll 4
    for (int j4 = 0; j4 < 16; ++j4) {
        float4 va = *(const float4*)&vs[lane * 68 + j4 * 4];
        float4 ua = *(const float4*)&us[lane * 68 + j4 * 4];
        #pragma unroll
        for (int jj = 0; jj < 4; ++jj) {
            float a  = (&va.x)[jj];
            float bb = (&ua.x)[jj];
            unsigned long long aa = pack2(a, a);
            unsigned long long bp = pack2(bb, bb);
            const float* mrow = &Msh[(j4 * 4 + jj) * 64 + wp * 4];
            #pragma unroll
            for (int p = 0; p < 2; ++p) {
                unsigned long long mm =
                    *(const unsigned long long*)(mrow + p * 2);  // bcast LDS.64
                accv[p] = ffma2(mm, aa, accv[p]);
                accu[p] = ffma2(mm, bp, accu[p]);
            }
        }
    }
    #pragma unroll
    for (int p = 0; p < 2; ++p) {
        float r0, r1, s0, s1;
        unpack2(r0, r1, accv[p]);
        unpack2(s0, s1, accu[p]);
        const int n0 = wp * 4 + p * 2;
        rvs[n0 * 32 + lane]       = r0;
        rvs[(n0 + 1) * 32 + lane] = r1;
        rus[n0 * 32 + lane]       = s0;
        rus[(n0 + 1) * 32 + lane] = s1;
    }
    __syncthreads();

    // ---- z_pb (b==0, eh==0): before phase 3, overlaps chip write phase -----
    if (b == 0 && eh == 0) {
        if (tid < 64) {
            float acc = 0.f;
            #pragma unroll
            for (int j = 0; j < 64; ++j) acc += Msh[j * 64 + tid] * osh[j];
            zp[tid] = 64.0f * acc;
        }
        __syncthreads();
        for (int idx = tid; idx < 4096; idx += 512) {
            int i = idx >> 6, j = idx & 63;
            out2[(size_t)idx * 16 + h] = zp[j] + zp[i];
        }
    }

    // ---- Phase 3: streaming float4 output ----------------------------------
    const int q  = tid & 7;                // float4 slot within 32-e half
    const int rg = tid >> 3;               // 0..63 (j)
    float* ob = out + ((size_t)b * STOT * NH + h) * NE + eh * 32;
    float4 a4 = *(const float4*)&rvs[rg * 32 + q * 4];   // j = rg, invariant
    #pragma unroll 4
    for (int r = 0; r < 64; ++r) {         // i = r
        float4 c4 = *(const float4*)&rus[r * 32 + q * 4];
        float4 o4 = make_float4(a4.x + c4.x, a4.y + c4.y, a4.z + c4.z, a4.w + c4.w);
        __stcs((float4*)&ob[((size_t)(r * 64 + rg)) * 1024 + q * 4], o4);
    }
}

// ---------------------------------------------------------------------------
extern "C" void kernel_launch(void* const* d_in, const int* in_sizes, int n_in,
                              void* d_out, int out_size) {
    const float* v  = (const float*)d_in[0];   // (8,4096,16,64) f32
    const float* w  = (const float*)d_in[1];   // (1,16,127) f32
    const float* o_ = (const float*)d_in[2];   // (64,) f32
    float* out  = (float*)d_out;
    float* out2 = out + (size_t)NB * STOT * NH * NE;   // z_pb region

    const int smem_bytes = (8704 * 2 + 4096) * 4;      // 86016 B -> 2 CTAs/SM

    cudaFuncSetAttribute(fftbias_fused,
                         cudaFuncAttributeMaxDynamicSharedMemorySize, smem_bytes);

    fftbias_fused<<<NB * NH * 2, 512, smem_bytes>>>(v, w, o_, out, out2);
}